// round 13
// baseline (speedup 1.0000x reference)
#include <cuda_runtime.h>
#include <cuda_bf16.h>

// Lp_Conv2D_BT: out[b,o,i,j] = max_{k<4} | w[o,k] - x_pad[b, c_k, i+di_k-1, j+dj_k-1] | + bias[o]
// edge padding (clamp), stride 1.
// x:(32,64,64,64) f32; weights:(128,4) f32; bias:(128,1,1) f32; conn_idx:(128,4) i32.
// out:(32,128,64,64) f32.
// R13: R8 body + persistent CTAs (grid = 6*148, grid-stride over planes) to
// remove wave-quantization / wave-transition losses.

namespace {
constexpr int HW   = 64;
constexpr int CIN  = 64;
constexpr int COUT = 128;
constexpr int CONN = 4;
constexpr int GRID = 888;               // 6 CTAs/SM * 148 SMs -> exactly one wave
}

__global__ __launch_bounds__(256) void lp_conv_bt_kernel(
    const float* __restrict__ x,
    const float* __restrict__ weights,
    const float* __restrict__ bias,
    const int*   __restrict__ conn_idx,
    float*       __restrict__ out,
    int nPlanes)
{
    const int t      = threadIdx.x;
    const int lane16 = t & 15;
    const int r0     = t >> 4;           // 0..15
    const bool laneLo = (lane16 == 0);
    const bool laneHi = (lane16 == 15);

    for (int p = blockIdx.x; p < nPlanes; p += GRID) {
        const int o = p & (COUT - 1);
        const int b = p >> 7;
        const float* xb = x + (size_t)b * CIN * (HW * HW);

        // Per-output-channel connection parameters (uniform across the block).
        const float* bp[CONN];
        int a0[CONN], a3[CONN], dc[CONN];
        float w[CONN];
#pragma unroll
        for (int k = 0; k < CONN; ++k) {
            const int idx = __ldg(conn_idx + o * CONN + k);   // [0, 576)
            const int c   = idx / 9;
            const int rem = idx - c * 9;
            const int di  = rem / 3;
            const int drk = di - 1;                            // {-1,0,1}
            dc[k] = (rem - di * 3) - 1;                        // {-1,0,1}
            w[k]  = __ldg(weights + o * CONN + k);
            bp[k] = xb + c * (HW * HW) + (r0 + drk) * HW + lane16 * 4;
            a0[k] = ((r0 + drk) < 0) ? HW : 0;                 // only r0==0, dr==-1
            a3[k] = ((r0 + 48 + drk) > HW - 1) ? -HW : 0;      // only r0==15, dr==+1
        }
        const float bs = __ldg(bias + o);

        // 16 max-accumulators: m[rb][j], all >= 0.
        float m[4][4];
#pragma unroll
        for (int rb = 0; rb < 4; ++rb)
#pragma unroll
            for (int j = 0; j < 4; ++j) m[rb][j] = 0.f;

        // k outer: 4 loads, ONE uniform dc branch, 4 straight-line row-blocks.
#pragma unroll
        for (int k = 0; k < CONN; ++k) {
            float4 v[4];
            v[0] = __ldg(reinterpret_cast<const float4*>(bp[k] + a0[k]));
            v[1] = __ldg(reinterpret_cast<const float4*>(bp[k] + 16 * HW));
            v[2] = __ldg(reinterpret_cast<const float4*>(bp[k] + 32 * HW));
            v[3] = __ldg(reinterpret_cast<const float4*>(bp[k] + 48 * HW + a3[k]));
            const float wk = w[k];

            if (dc[k] == 0) {
#pragma unroll
                for (int rb = 0; rb < 4; ++rb) {
                    m[rb][0] = fmaxf(m[rb][0], fabsf(wk - v[rb].x));
                    m[rb][1] = fmaxf(m[rb][1], fabsf(wk - v[rb].y));
                    m[rb][2] = fmaxf(m[rb][2], fabsf(wk - v[rb].z));
                    m[rb][3] = fmaxf(m[rb][3], fabsf(wk - v[rb].w));
                }
            } else if (dc[k] > 0) {
#pragma unroll
                for (int rb = 0; rb < 4; ++rb) {
                    // cols j0+1..j0+4 ; j0+4 = next lane's v.x (col 64 -> clamp 63 = v.w)
                    float e = __shfl_down_sync(0xffffffffu, v[rb].x, 1, 16);
                    if (laneHi) e = v[rb].w;
                    m[rb][0] = fmaxf(m[rb][0], fabsf(wk - v[rb].y));
                    m[rb][1] = fmaxf(m[rb][1], fabsf(wk - v[rb].z));
                    m[rb][2] = fmaxf(m[rb][2], fabsf(wk - v[rb].w));
                    m[rb][3] = fmaxf(m[rb][3], fabsf(wk - e));
                }
            } else {
#pragma unroll
                for (int rb = 0; rb < 4; ++rb) {
                    // cols j0-1..j0+2 ; j0-1 = prev lane's v.w (col -1 -> clamp 0 = v.x)
                    float e = __shfl_up_sync(0xffffffffu, v[rb].w, 1, 16);
                    if (laneLo) e = v[rb].x;
                    m[rb][0] = fmaxf(m[rb][0], fabsf(wk - e));
                    m[rb][1] = fmaxf(m[rb][1], fabsf(wk - v[rb].x));
                    m[rb][2] = fmaxf(m[rb][2], fabsf(wk - v[rb].y));
                    m[rb][3] = fmaxf(m[rb][3], fabsf(wk - v[rb].z));
                }
            }
        }

        // Epilogue: bias + streaming float4 stores (contiguous per lane).
        float4* po = reinterpret_cast<float4*>(out + (size_t)p * (HW * HW))
                     + r0 * 16 + lane16;
#pragma unroll
        for (int rb = 0; rb < 4; ++rb) {
            __stcs(po + rb * 16 * 16,
                   make_float4(m[rb][0] + bs, m[rb][1] + bs,
                               m[rb][2] + bs, m[rb][3] + bs));
        }
    }
}

extern "C" void kernel_launch(void* const* d_in, const int* in_sizes, int n_in,
                              void* d_out, int out_size) {
    const float* x       = (const float*)d_in[0];
    const float* weights = (const float*)d_in[1];
    const float* bias    = (const float*)d_in[2];
    const int*   conn    = (const int*)d_in[3];
    float*       out     = (float*)d_out;

    const int B = in_sizes[0] / (CIN * HW * HW);   // 32
    lp_conv_bt_kernel<<<GRID, 256>>>(x, weights, bias, conn, out, B * COUT);
}

// round 14
// speedup vs baseline: 1.0732x; 1.0732x over previous
#include <cuda_runtime.h>
#include <cuda_bf16.h>

// Lp_Conv2D_BT: out[b,o,i,j] = max_{k<4} | w[o,k] - x_pad[b, c_k, i+di_k-1, j+dj_k-1] | + bias[o]
// edge padding (clamp), stride 1.
// x:(32,64,64,64) f32; weights:(128,4) f32; bias:(128,1,1) f32; conn_idx:(128,4) i32.
// out:(32,128,64,64) f32.
// R14: R8 body + vectorized prologue (int4 conn / float4 weights), regs pinned.

namespace {
constexpr int HW   = 64;
constexpr int CIN  = 64;
constexpr int COUT = 128;
constexpr int CONN = 4;
}

__global__ __launch_bounds__(256, 6) void lp_conv_bt_kernel(
    const float* __restrict__ x,
    const float* __restrict__ weights,
    const float* __restrict__ bias,
    const int*   __restrict__ conn_idx,
    float*       __restrict__ out)
{
    const int blk = blockIdx.x;          // blk = b*COUT + o
    const int o   = blk & (COUT - 1);
    const int b   = blk >> 7;
    const int t   = threadIdx.x;

    const int lane16 = t & 15;
    const int r0     = t >> 4;           // 0..15
    const bool laneLo = (lane16 == 0);
    const bool laneHi = (lane16 == 15);

    const float* xb = x + (size_t)b * CIN * (HW * HW);

    // Vectorized per-o parameter fetch: 1x LDG.128 conn, 1x LDG.128 weights,
    // 1x LDG.32 bias -- all independent, issued back-to-back.
    const int4   ci = __ldg(reinterpret_cast<const int4*>(conn_idx + o * CONN));
    const float4 wr = __ldg(reinterpret_cast<const float4*>(weights + o * CONN));
    const float  bs = __ldg(bias + o);

    const int   cik[CONN] = {ci.x, ci.y, ci.z, ci.w};
    const float w[CONN]   = {wr.x, wr.y, wr.z, wr.w};

    const float* bp[CONN];
    int a0[CONN], a3[CONN], dc[CONN];
#pragma unroll
    for (int k = 0; k < CONN; ++k) {
        const int idx = cik[k];                            // [0, 576)
        const int c   = idx / 9;
        const int rem = idx - c * 9;
        const int di  = rem / 3;
        const int drk = di - 1;                            // {-1,0,1}
        dc[k] = (rem - di * 3) - 1;                        // {-1,0,1}
        bp[k] = xb + c * (HW * HW) + (r0 + drk) * HW + lane16 * 4;
        a0[k] = ((r0 + drk) < 0) ? HW : 0;                 // only r0==0, dr==-1
        a3[k] = ((r0 + 48 + drk) > HW - 1) ? -HW : 0;      // only r0==15, dr==+1
    }

    // 16 max-accumulators: m[rb][j], all >= 0.
    float m[4][4];
#pragma unroll
    for (int rb = 0; rb < 4; ++rb)
#pragma unroll
        for (int j = 0; j < 4; ++j) m[rb][j] = 0.f;

    // k outer: 4 loads, ONE uniform dc branch, 4 straight-line row-blocks.
#pragma unroll
    for (int k = 0; k < CONN; ++k) {
        float4 v[4];
        v[0] = __ldg(reinterpret_cast<const float4*>(bp[k] + a0[k]));
        v[1] = __ldg(reinterpret_cast<const float4*>(bp[k] + 16 * HW));
        v[2] = __ldg(reinterpret_cast<const float4*>(bp[k] + 32 * HW));
        v[3] = __ldg(reinterpret_cast<const float4*>(bp[k] + 48 * HW + a3[k]));
        const float wk = w[k];

        if (dc[k] == 0) {
#pragma unroll
            for (int rb = 0; rb < 4; ++rb) {
                m[rb][0] = fmaxf(m[rb][0], fabsf(wk - v[rb].x));
                m[rb][1] = fmaxf(m[rb][1], fabsf(wk - v[rb].y));
                m[rb][2] = fmaxf(m[rb][2], fabsf(wk - v[rb].z));
                m[rb][3] = fmaxf(m[rb][3], fabsf(wk - v[rb].w));
            }
        } else if (dc[k] > 0) {
#pragma unroll
            for (int rb = 0; rb < 4; ++rb) {
                // cols j0+1..j0+4 ; j0+4 = next lane's v.x (col 64 -> clamp 63 = v.w)
                float e = __shfl_down_sync(0xffffffffu, v[rb].x, 1, 16);
                if (laneHi) e = v[rb].w;
                m[rb][0] = fmaxf(m[rb][0], fabsf(wk - v[rb].y));
                m[rb][1] = fmaxf(m[rb][1], fabsf(wk - v[rb].z));
                m[rb][2] = fmaxf(m[rb][2], fabsf(wk - v[rb].w));
                m[rb][3] = fmaxf(m[rb][3], fabsf(wk - e));
            }
        } else {
#pragma unroll
            for (int rb = 0; rb < 4; ++rb) {
                // cols j0-1..j0+2 ; j0-1 = prev lane's v.w (col -1 -> clamp 0 = v.x)
                float e = __shfl_up_sync(0xffffffffu, v[rb].w, 1, 16);
                if (laneLo) e = v[rb].x;
                m[rb][0] = fmaxf(m[rb][0], fabsf(wk - e));
                m[rb][1] = fmaxf(m[rb][1], fabsf(wk - v[rb].x));
                m[rb][2] = fmaxf(m[rb][2], fabsf(wk - v[rb].y));
                m[rb][3] = fmaxf(m[rb][3], fabsf(wk - v[rb].z));
            }
        }
    }

    // Epilogue: bias + streaming float4 stores (contiguous per lane).
    float4* po = reinterpret_cast<float4*>(out + (size_t)blk * (HW * HW)) + r0 * 16 + lane16;
#pragma unroll
    for (int rb = 0; rb < 4; ++rb) {
        __stcs(po + rb * 16 * 16,
               make_float4(m[rb][0] + bs, m[rb][1] + bs, m[rb][2] + bs, m[rb][3] + bs));
    }
}

extern "C" void kernel_launch(void* const* d_in, const int* in_sizes, int n_in,
                              void* d_out, int out_size) {
    const float* x       = (const float*)d_in[0];
    const float* weights = (const float*)d_in[1];
    const float* bias    = (const float*)d_in[2];
    const int*   conn    = (const int*)d_in[3];
    float*       out     = (float*)d_out;

    const int B = in_sizes[0] / (CIN * HW * HW);   // 32
    lp_conv_bt_kernel<<<B * COUT, 256>>>(x, weights, bias, conn, out);
}

// round 15
// speedup vs baseline: 1.1293x; 1.0523x over previous
#include <cuda_runtime.h>
#include <cuda_bf16.h>

// Lp_Conv2D_BT: out[b,o,i,j] = max_{k<4} | w[o,k] - x_pad[b, c_k, i+di_k-1, j+dj_k-1] | + bias[o]
// edge padding (clamp), stride 1.
// x:(32,64,64,64) f32; weights:(128,4) f32; bias:(128,1,1) f32; conn_idx:(128,4) i32.
// out:(32,128,64,64) f32.
// R15: R14 body + max-L1 carveout (kernel uses no smem; grow L1D to 228KB for
// cross-CTA channel-plane reuse on the gather path).

namespace {
constexpr int HW   = 64;
constexpr int CIN  = 64;
constexpr int COUT = 128;
constexpr int CONN = 4;
}

__global__ __launch_bounds__(256, 6) void lp_conv_bt_kernel(
    const float* __restrict__ x,
    const float* __restrict__ weights,
    const float* __restrict__ bias,
    const int*   __restrict__ conn_idx,
    float*       __restrict__ out)
{
    const int blk = blockIdx.x;          // blk = b*COUT + o
    const int o   = blk & (COUT - 1);
    const int b   = blk >> 7;
    const int t   = threadIdx.x;

    const int lane16 = t & 15;
    const int r0     = t >> 4;           // 0..15
    const bool laneLo = (lane16 == 0);
    const bool laneHi = (lane16 == 15);

    const float* xb = x + (size_t)b * CIN * (HW * HW);

    // Vectorized per-o parameter fetch: 1x LDG.128 conn, 1x LDG.128 weights,
    // 1x LDG.32 bias -- all independent, issued back-to-back.
    const int4   ci = __ldg(reinterpret_cast<const int4*>(conn_idx + o * CONN));
    const float4 wr = __ldg(reinterpret_cast<const float4*>(weights + o * CONN));
    const float  bs = __ldg(bias + o);

    const int   cik[CONN] = {ci.x, ci.y, ci.z, ci.w};
    const float w[CONN]   = {wr.x, wr.y, wr.z, wr.w};

    const float* bp[CONN];
    int a0[CONN], a3[CONN], dc[CONN];
#pragma unroll
    for (int k = 0; k < CONN; ++k) {
        const int idx = cik[k];                            // [0, 576)
        const int c   = idx / 9;
        const int rem = idx - c * 9;
        const int di  = rem / 3;
        const int drk = di - 1;                            // {-1,0,1}
        dc[k] = (rem - di * 3) - 1;                        // {-1,0,1}
        bp[k] = xb + c * (HW * HW) + (r0 + drk) * HW + lane16 * 4;
        a0[k] = ((r0 + drk) < 0) ? HW : 0;                 // only r0==0, dr==-1
        a3[k] = ((r0 + 48 + drk) > HW - 1) ? -HW : 0;      // only r0==15, dr==+1
    }

    // 16 max-accumulators: m[rb][j], all >= 0.
    float m[4][4];
#pragma unroll
    for (int rb = 0; rb < 4; ++rb)
#pragma unroll
        for (int j = 0; j < 4; ++j) m[rb][j] = 0.f;

    // k outer: 4 loads, ONE uniform dc branch, 4 straight-line row-blocks.
#pragma unroll
    for (int k = 0; k < CONN; ++k) {
        float4 v[4];
        v[0] = __ldg(reinterpret_cast<const float4*>(bp[k] + a0[k]));
        v[1] = __ldg(reinterpret_cast<const float4*>(bp[k] + 16 * HW));
        v[2] = __ldg(reinterpret_cast<const float4*>(bp[k] + 32 * HW));
        v[3] = __ldg(reinterpret_cast<const float4*>(bp[k] + 48 * HW + a3[k]));
        const float wk = w[k];

        if (dc[k] == 0) {
#pragma unroll
            for (int rb = 0; rb < 4; ++rb) {
                m[rb][0] = fmaxf(m[rb][0], fabsf(wk - v[rb].x));
                m[rb][1] = fmaxf(m[rb][1], fabsf(wk - v[rb].y));
                m[rb][2] = fmaxf(m[rb][2], fabsf(wk - v[rb].z));
                m[rb][3] = fmaxf(m[rb][3], fabsf(wk - v[rb].w));
            }
        } else if (dc[k] > 0) {
#pragma unroll
            for (int rb = 0; rb < 4; ++rb) {
                // cols j0+1..j0+4 ; j0+4 = next lane's v.x (col 64 -> clamp 63 = v.w)
                float e = __shfl_down_sync(0xffffffffu, v[rb].x, 1, 16);
                if (laneHi) e = v[rb].w;
                m[rb][0] = fmaxf(m[rb][0], fabsf(wk - v[rb].y));
                m[rb][1] = fmaxf(m[rb][1], fabsf(wk - v[rb].z));
                m[rb][2] = fmaxf(m[rb][2], fabsf(wk - v[rb].w));
                m[rb][3] = fmaxf(m[rb][3], fabsf(wk - e));
            }
        } else {
#pragma unroll
            for (int rb = 0; rb < 4; ++rb) {
                // cols j0-1..j0+2 ; j0-1 = prev lane's v.w (col -1 -> clamp 0 = v.x)
                float e = __shfl_up_sync(0xffffffffu, v[rb].w, 1, 16);
                if (laneLo) e = v[rb].x;
                m[rb][0] = fmaxf(m[rb][0], fabsf(wk - e));
                m[rb][1] = fmaxf(m[rb][1], fabsf(wk - v[rb].x));
                m[rb][2] = fmaxf(m[rb][2], fabsf(wk - v[rb].y));
                m[rb][3] = fmaxf(m[rb][3], fabsf(wk - v[rb].z));
            }
        }
    }

    // Epilogue: bias + streaming float4 stores (contiguous per lane).
    float4* po = reinterpret_cast<float4*>(out + (size_t)blk * (HW * HW)) + r0 * 16 + lane16;
#pragma unroll
    for (int rb = 0; rb < 4; ++rb) {
        __stcs(po + rb * 16 * 16,
               make_float4(m[rb][0] + bs, m[rb][1] + bs, m[rb][2] + bs, m[rb][3] + bs));
    }
}

extern "C" void kernel_launch(void* const* d_in, const int* in_sizes, int n_in,
                              void* d_out, int out_size) {
    const float* x       = (const float*)d_in[0];
    const float* weights = (const float*)d_in[1];
    const float* bias    = (const float*)d_in[2];
    const int*   conn    = (const int*)d_in[3];
    float*       out     = (float*)d_out;

    // Kernel uses no shared memory: ask for the maximum L1D carveout so the
    // gather working set (channel planes shared across resident CTAs) caches.
    // Host-side attribute set; not a stream operation -> graph-capture safe,
    // idempotent and deterministic.
    cudaFuncSetAttribute(lp_conv_bt_kernel,
                         cudaFuncAttributePreferredSharedMemoryCarveout,
                         cudaSharedmemCarveoutMaxL1);

    const int B = in_sizes[0] / (CIN * HW * HW);   // 32
    lp_conv_bt_kernel<<<B * COUT, 256>>>(x, weights, bias, conn, out);
}

// round 16
// speedup vs baseline: 1.1645x; 1.0312x over previous
#include <cuda_runtime.h>
#include <cuda_bf16.h>

// Lp_Conv2D_BT: out[b,o,i,j] = max_{k<4} | w[o,k] - x_pad[b, c_k, i+di_k-1, j+dj_k-1] | + bias[o]
// edge padding (clamp), stride 1.
// x:(32,64,64,64) f32; weights:(128,4) f32; bias:(128,1,1) f32; conn_idx:(128,4) i32.
// out:(32,128,64,64) f32.
// R16: R15 body + L1::evict_last policy on the x gathers (x planes are shared
// across resident CTAs; keep them resident over streaming traffic).

namespace {
constexpr int HW   = 64;
constexpr int CIN  = 64;
constexpr int COUT = 128;
constexpr int CONN = 4;
}

__device__ __forceinline__ float4 ldg_evict_last_v4(const float* p) {
    float4 v;
    asm volatile("ld.global.nc.L1::evict_last.v4.f32 {%0,%1,%2,%3}, [%4];"
                 : "=f"(v.x), "=f"(v.y), "=f"(v.z), "=f"(v.w)
                 : "l"(p));
    return v;
}

__global__ __launch_bounds__(256, 6) void lp_conv_bt_kernel(
    const float* __restrict__ x,
    const float* __restrict__ weights,
    const float* __restrict__ bias,
    const int*   __restrict__ conn_idx,
    float*       __restrict__ out)
{
    const int blk = blockIdx.x;          // blk = b*COUT + o
    const int o   = blk & (COUT - 1);
    const int b   = blk >> 7;
    const int t   = threadIdx.x;

    const int lane16 = t & 15;
    const int r0     = t >> 4;           // 0..15
    const bool laneLo = (lane16 == 0);
    const bool laneHi = (lane16 == 15);

    const float* xb = x + (size_t)b * CIN * (HW * HW);

    // Vectorized per-o parameter fetch: 1x LDG.128 conn, 1x LDG.128 weights,
    // 1x LDG.32 bias -- all independent, issued back-to-back.
    const int4   ci = __ldg(reinterpret_cast<const int4*>(conn_idx + o * CONN));
    const float4 wr = __ldg(reinterpret_cast<const float4*>(weights + o * CONN));
    const float  bs = __ldg(bias + o);

    const int   cik[CONN] = {ci.x, ci.y, ci.z, ci.w};
    const float w[CONN]   = {wr.x, wr.y, wr.z, wr.w};

    const float* bp[CONN];
    int a0[CONN], a3[CONN], dc[CONN];
#pragma unroll
    for (int k = 0; k < CONN; ++k) {
        const int idx = cik[k];                            // [0, 576)
        const int c   = idx / 9;
        const int rem = idx - c * 9;
        const int di  = rem / 3;
        const int drk = di - 1;                            // {-1,0,1}
        dc[k] = (rem - di * 3) - 1;                        // {-1,0,1}
        bp[k] = xb + c * (HW * HW) + (r0 + drk) * HW + lane16 * 4;
        a0[k] = ((r0 + drk) < 0) ? HW : 0;                 // only r0==0, dr==-1
        a3[k] = ((r0 + 48 + drk) > HW - 1) ? -HW : 0;      // only r0==15, dr==+1
    }

    // 16 max-accumulators: m[rb][j], all >= 0.
    float m[4][4];
#pragma unroll
    for (int rb = 0; rb < 4; ++rb)
#pragma unroll
        for (int j = 0; j < 4; ++j) m[rb][j] = 0.f;

    // k outer: 4 loads, ONE uniform dc branch, 4 straight-line row-blocks.
#pragma unroll
    for (int k = 0; k < CONN; ++k) {
        float4 v[4];
        v[0] = ldg_evict_last_v4(bp[k] + a0[k]);
        v[1] = ldg_evict_last_v4(bp[k] + 16 * HW);
        v[2] = ldg_evict_last_v4(bp[k] + 32 * HW);
        v[3] = ldg_evict_last_v4(bp[k] + 48 * HW + a3[k]);
        const float wk = w[k];

        if (dc[k] == 0) {
#pragma unroll
            for (int rb = 0; rb < 4; ++rb) {
                m[rb][0] = fmaxf(m[rb][0], fabsf(wk - v[rb].x));
                m[rb][1] = fmaxf(m[rb][1], fabsf(wk - v[rb].y));
                m[rb][2] = fmaxf(m[rb][2], fabsf(wk - v[rb].z));
                m[rb][3] = fmaxf(m[rb][3], fabsf(wk - v[rb].w));
            }
        } else if (dc[k] > 0) {
#pragma unroll
            for (int rb = 0; rb < 4; ++rb) {
                // cols j0+1..j0+4 ; j0+4 = next lane's v.x (col 64 -> clamp 63 = v.w)
                float e = __shfl_down_sync(0xffffffffu, v[rb].x, 1, 16);
                if (laneHi) e = v[rb].w;
                m[rb][0] = fmaxf(m[rb][0], fabsf(wk - v[rb].y));
                m[rb][1] = fmaxf(m[rb][1], fabsf(wk - v[rb].z));
                m[rb][2] = fmaxf(m[rb][2], fabsf(wk - v[rb].w));
                m[rb][3] = fmaxf(m[rb][3], fabsf(wk - e));
            }
        } else {
#pragma unroll
            for (int rb = 0; rb < 4; ++rb) {
                // cols j0-1..j0+2 ; j0-1 = prev lane's v.w (col -1 -> clamp 0 = v.x)
                float e = __shfl_up_sync(0xffffffffu, v[rb].w, 1, 16);
                if (laneLo) e = v[rb].x;
                m[rb][0] = fmaxf(m[rb][0], fabsf(wk - e));
                m[rb][1] = fmaxf(m[rb][1], fabsf(wk - v[rb].x));
                m[rb][2] = fmaxf(m[rb][2], fabsf(wk - v[rb].y));
                m[rb][3] = fmaxf(m[rb][3], fabsf(wk - v[rb].z));
            }
        }
    }

    // Epilogue: bias + streaming float4 stores (contiguous per lane).
    float4* po = reinterpret_cast<float4*>(out + (size_t)blk * (HW * HW)) + r0 * 16 + lane16;
#pragma unroll
    for (int rb = 0; rb < 4; ++rb) {
        __stcs(po + rb * 16 * 16,
               make_float4(m[rb][0] + bs, m[rb][1] + bs, m[rb][2] + bs, m[rb][3] + bs));
    }
}

extern "C" void kernel_launch(void* const* d_in, const int* in_sizes, int n_in,
                              void* d_out, int out_size) {
    const float* x       = (const float*)d_in[0];
    const float* weights = (const float*)d_in[1];
    const float* bias    = (const float*)d_in[2];
    const int*   conn    = (const int*)d_in[3];
    float*       out     = (float*)d_out;

    // No shared memory used: request max L1D carveout (host-side attribute,
    // graph-capture safe, deterministic).
    cudaFuncSetAttribute(lp_conv_bt_kernel,
                         cudaFuncAttributePreferredSharedMemoryCarveout,
                         cudaSharedmemCarveoutMaxL1);

    const int B = in_sizes[0] / (CIN * HW * HW);   // 32
    lp_conv_bt_kernel<<<B * COUT, 256>>>(x, weights, bias, conn, out);
}